// round 17
// baseline (speedup 1.0000x reference)
#include <cuda_runtime.h>
#include <cuda_fp16.h>
#include <cstdint>
#include <math.h>

#define D_MODEL 1024
#define NHEAD 16
#define HEAD_DIM 64
#define BATCH 2
#define SEQ 2048
#define MTOT (BATCH*SEQ)   // 4096

// Scratch (allocation-free rule: __device__ globals)
__device__ __half g_Q[MTOT * D_MODEL];
__device__ __half g_K[MTOT * D_MODEL];
__device__ __half g_Vt[MTOT * D_MODEL];  // V projection, TRANSPOSED: [b][channel][token]
__device__ __half g_Attn[MTOT * D_MODEL];
// half pre-conversions of inputs / weights
__device__ __half g_hXq[MTOT * D_MODEL];
__device__ __half g_hXk[MTOT * D_MODEL];
__device__ __half g_hXv[MTOT * D_MODEL];
__device__ __half g_hWq[D_MODEL * D_MODEL];
__device__ __half g_hWk[D_MODEL * D_MODEL];
__device__ __half g_hWv[D_MODEL * D_MODEL];
__device__ __half g_hWo[D_MODEL * D_MODEL];

// ---------------------------------------------------------------------------
// helpers
// ---------------------------------------------------------------------------
__device__ __forceinline__ void mma16h(float* c, const unsigned* a,
                                       unsigned b0, unsigned b1) {
    asm volatile(
        "mma.sync.aligned.m16n8k16.row.col.f32.f16.f16.f32 "
        "{%0,%1,%2,%3}, {%4,%5,%6,%7}, {%8,%9}, {%0,%1,%2,%3};"
        : "+f"(c[0]), "+f"(c[1]), "+f"(c[2]), "+f"(c[3])
        : "r"(a[0]), "r"(a[1]), "r"(a[2]), "r"(a[3]), "r"(b0), "r"(b1));
}

__device__ __forceinline__ void ldsm4(unsigned& r0, unsigned& r1,
                                      unsigned& r2, unsigned& r3, const void* p) {
    unsigned addr = (unsigned)__cvta_generic_to_shared(p);
    asm volatile("ldmatrix.sync.aligned.m8n8.x4.shared.b16 {%0,%1,%2,%3}, [%4];"
        : "=r"(r0), "=r"(r1), "=r"(r2), "=r"(r3) : "r"(addr));
}

__device__ __forceinline__ void cp_async16(void* dst, const void* src) {
    unsigned int d = (unsigned int)__cvta_generic_to_shared(dst);
    asm volatile("cp.async.cg.shared.global [%0], [%1], 16;" :: "r"(d), "l"(src));
}
#define CP_COMMIT() asm volatile("cp.async.commit_group;")
#define CP_WAIT1()  asm volatile("cp.async.wait_group 1;")

// ---------------------------------------------------------------------------
// f32 -> f16 conversion, all 7 tensors in one launch (z = 0..6).
// ---------------------------------------------------------------------------
__global__ void f2h_all(
    const float* __restrict__ x0, const float* __restrict__ x1,
    const float* __restrict__ x2, const float* __restrict__ w0,
    const float* __restrict__ w1, const float* __restrict__ w2,
    const float* __restrict__ w3,
    __half* __restrict__ y0, __half* __restrict__ y1, __half* __restrict__ y2,
    __half* __restrict__ v0, __half* __restrict__ v1, __half* __restrict__ v2,
    __half* __restrict__ v3)
{
    const int z = blockIdx.z;
    if (z >= 3 && blockIdx.x >= (D_MODEL * D_MODEL / 8) / 256) return;
    const float* s; __half* d;
    switch (z) {
        case 0: s = x0; d = y0; break;
        case 1: s = x1; d = y1; break;
        case 2: s = x2; d = y2; break;
        case 3: s = w0; d = v0; break;
        case 4: s = w1; d = v1; break;
        case 5: s = w2; d = v2; break;
        default: s = w3; d = v3; break;
    }
    const int i = blockIdx.x * blockDim.x + threadIdx.x;
    float4 a = ((const float4*)s)[2 * i];
    float4 b = ((const float4*)s)[2 * i + 1];
    __half2 h[4] = { __floats2half2_rn(a.x, a.y), __floats2half2_rn(a.z, a.w),
                     __floats2half2_rn(b.x, b.y), __floats2half2_rn(b.z, b.w) };
    ((float4*)d)[i] = *(float4*)h;
}

// ---------------------------------------------------------------------------
// fp16 GEMM, 64x128 CTA tile, 32x32 warp tiles, 3 CTAs/SM (24 warps):
//   C = (A @ W^T + bias) * scale     (fp32 accumulators)
// 3-buffer cp.async ring (wait_group 1), one sync per k-tile, commit every
// iteration. Per thread per tile: 3 cp.async.16B (1 A, 2 W).
// OM: 0 = f32 [token][channel], 1 = half [token][channel],
//     2 = half TRANSPOSED [b][channel][token] (Vt)
// smem stride 40 halves: ldmatrix phases conflict-free (R14-proven).
// ---------------------------------------------------------------------------
#define HS2 40
#define GEMM_AT (64 * HS2)            // A tile halves per buffer
#define GEMM_WT (128 * HS2)           // W tile halves per buffer
#define GEMMH_SMEM (3 * (GEMM_AT + GEMM_WT) * (int)sizeof(__half))  // 46080

template<int OM>
__global__ __launch_bounds__(256, 3) void gemm_hcp(
    const __half* __restrict__ A, const __half* __restrict__ W,
    const float* __restrict__ bias, float scale, void* __restrict__ Cv)
{
    extern __shared__ __half smh[];
    __half* As = smh;                   // [3][64*HS2]
    __half* Ws = smh + 3 * GEMM_AT;     // [3][128*HS2]

    const int m0 = blockIdx.y * 64;
    const int n0 = blockIdx.x * 128;
    const int t  = threadIdx.x;
    const int wid = t >> 5, lane = t & 31;
    const int g4 = lane >> 2, q4 = lane & 3;
    const int wm = wid >> 2;          // 0..1  -> m offset wm*32
    const int wn = wid & 3;           // 0..3  -> n offset wn*32

    float c[2][4][4];
    #pragma unroll
    for (int i = 0; i < 2; i++)
        #pragma unroll
        for (int j = 0; j < 4; j++)
            c[i][j][0] = c[i][j][1] = c[i][j][2] = c[i][j][3] = 0.f;

    // ldmatrix per-lane offsets (half units)
    const int aoff = (lane & 15) * HS2 + (lane >> 4) * 8;
    const int boff = ((lane & 7) + ((lane >> 4) << 3)) * HS2 + ((lane >> 3) & 1) * 8;

    const int NKT = D_MODEL / 32;

    // stage k-tile kt into ring buffer b3: A 1 op, W 2 ops per thread
    auto stage = [&](int kt, int b3) {
        __half* Ab = As + b3 * GEMM_AT;
        __half* Wb = Ws + b3 * GEMM_WT;
        const int ke = kt * 32;
        {
            const int row = t >> 2, seg = (t & 3) * 8;   // 64 rows x 4 segs
            cp_async16(&Ab[row * HS2 + seg],
                       A + (size_t)(m0 + row) * D_MODEL + ke + seg);
        }
        #pragma unroll
        for (int i = 0; i < 2; i++) {
            const int cid = t + i * 256;                 // 128 rows x 4 segs
            const int row = cid >> 2, seg = (cid & 3) * 8;
            cp_async16(&Wb[row * HS2 + seg],
                       W + (size_t)(n0 + row) * D_MODEL + ke + seg);
        }
    };

    stage(0, 0); CP_COMMIT();
    stage(1, 1); CP_COMMIT();

    int buf = 0;
    for (int kt = 0; kt < NKT; kt++) {
        CP_WAIT1();          // tile kt resident; kt+1 still in flight
        __syncthreads();     // readers of buf (kt+2)%3 (from iter kt-1) done

        const int nb = (buf + 2 >= 3) ? buf - 1 : buf + 2;
        if (kt + 2 < NKT) stage(kt + 2, nb);
        CP_COMMIT();         // commit every iteration (group counting)

        const __half* aB = As + buf * GEMM_AT + (wm * 32) * HS2 + aoff;
        const __half* bB = Ws + buf * GEMM_WT + (wn * 32) * HS2 + boff;
        #pragma unroll
        for (int kk = 0; kk < 2; kk++) {
            unsigned a[2][4];
            #pragma unroll
            for (int i = 0; i < 2; i++)
                ldsm4(a[i][0], a[i][1], a[i][2], a[i][3],
                      aB + i * 16 * HS2 + kk * 16);
            unsigned rb[8];
            ldsm4(rb[0], rb[1], rb[2], rb[3], bB + kk * 16);              // j=0,1
            ldsm4(rb[4], rb[5], rb[6], rb[7], bB + 16 * HS2 + kk * 16);   // j=2,3
            #pragma unroll
            for (int j = 0; j < 4; j++) {
                #pragma unroll
                for (int i = 0; i < 2; i++)
                    mma16h(c[i][j], a[i], rb[j * 2], rb[j * 2 + 1]);
            }
        }
        buf = (buf + 1 == 3) ? 0 : buf + 1;
    }

    // ---- epilogue: direct STG from fragments, bias in registers ----
    #pragma unroll
    for (int j = 0; j < 4; j++) {
        const int col = n0 + wn * 32 + j * 8 + 2 * q4;
        const float2 bb = *(const float2*)&bias[col];
        #pragma unroll
        for (int i = 0; i < 2; i++) {
            const int row = m0 + wm * 32 + i * 16 + g4;
            float2 v0, v1;
            v0.x = (c[i][j][0] + bb.x) * scale;
            v0.y = (c[i][j][1] + bb.y) * scale;
            v1.x = (c[i][j][2] + bb.x) * scale;
            v1.y = (c[i][j][3] + bb.y) * scale;
            if (OM == 0) {
                float* C = (float*)Cv;
                *(float2*)&C[(size_t)row * D_MODEL + col] = v0;
                *(float2*)&C[(size_t)(row + 8) * D_MODEL + col] = v1;
            } else if (OM == 1) {
                __half* C = (__half*)Cv;
                *(__half2*)(C + (size_t)row * D_MODEL + col) =
                    __floats2half2_rn(v0.x, v0.y);
                *(__half2*)(C + (size_t)(row + 8) * D_MODEL + col) =
                    __floats2half2_rn(v1.x, v1.y);
            } else {
                __half* C = (__half*)Cv;
                const int b0i = row >> 11, tl0 = row & 2047;
                const int b1i = (row + 8) >> 11, tl1 = (row + 8) & 2047;
                C[((size_t)b0i * D_MODEL + col)     * SEQ + tl0] = __float2half_rn(v0.x);
                C[((size_t)b0i * D_MODEL + col + 1) * SEQ + tl0] = __float2half_rn(v0.y);
                C[((size_t)b1i * D_MODEL + col)     * SEQ + tl1] = __float2half_rn(v1.x);
                C[((size_t)b1i * D_MODEL + col + 1) * SEQ + tl1] = __float2half_rn(v1.y);
            }
        }
    }
}

// ---------------------------------------------------------------------------
// Flash attention (R13/14, unchanged): fp16 mma.m16n8k16, fp32 softmax.
// ---------------------------------------------------------------------------
#define HS 72
#define NTILES (SEQ / 64)
#define ATTN_SMEM ((128*HS + 2*64*HS + 2*64*HS) * (int)sizeof(__half))  // 55296

__global__ __launch_bounds__(256, 2) void attn_h(
    const __half* __restrict__ Qb, const __half* __restrict__ Kb,
    const __half* __restrict__ Vt, __half* __restrict__ Ob)
{
    extern __shared__ __half smh[];
    __half* Ps   = smh;                      // [128][HS]  (Q staging, then P)
    __half* Kbuf = Ps + 128 * HS;            // [2][64][HS]
    __half* Vbuf = Kbuf + 2 * 64 * HS;       // [2][64][HS]

    const int qt = blockIdx.x, h = blockIdx.y, b = blockIdx.z;
    const int t = threadIdx.x, w = t >> 5, lane = t & 31;
    const int g4 = lane >> 2, q4 = lane & 3;
    const int base_q = b * SEQ + qt * 128;
    const int hcol = h * HEAD_DIM;

    const int koff = ((lane & 7) + ((lane >> 4) << 3)) * HS + ((lane >> 3) & 1) * 8;
    const int poff = (lane & 15) * HS + (lane >> 4) * 8;

    const __half* Vbase = Vt + ((size_t)b * D_MODEL + hcol) * SEQ;

    {
        #pragma unroll
        for (int i = 0; i < 2; i++) {
            const int cid = t + i * 256;
            const int row = cid >> 3, seg = (cid & 7) * 8;
            cp_async16(&Kbuf[row * HS + seg],
                       Kb + (size_t)(b * SEQ + row) * D_MODEL + hcol + seg);
            cp_async16(&Vbuf[row * HS + seg],
                       Vbase + (size_t)row * SEQ + seg);
        }
    }
    CP_COMMIT();

    {
        const int r = t >> 1;
        const int c0 = (t & 1) * 32;
        #pragma unroll
        for (int i = 0; i < 4; i++)
            *(float4*)&Ps[r * HS + c0 + i * 8] =
                *(const float4*)(Qb + (size_t)(base_q + r) * D_MODEL + hcol + c0 + i * 8);
    }
    __syncwarp();

    unsigned qa[4][4];
    {
        const __half* qB = Ps + (w * 16) * HS + poff;
        #pragma unroll
        for (int kk = 0; kk < 4; kk++)
            ldsm4(qa[kk][0], qa[kk][1], qa[kk][2], qa[kk][3], qB + kk * 16);
    }
    __syncwarp();

    float of[8][4];
    #pragma unroll
    for (int n = 0; n < 8; n++)
        of[n][0] = of[n][1] = of[n][2] = of[n][3] = 0.f;
    float m0r = -1e30f, m1r = -1e30f, l0r = 0.f, l1r = 0.f;

    for (int jt = 0; jt < NTILES; jt++) {
        __half* Kc = Kbuf + (jt & 1) * 64 * HS;
        __half* Vc = Vbuf + (jt & 1) * 64 * HS;

        if (jt + 1 < NTILES) {
            __half* Kn = Kbuf + ((jt + 1) & 1) * 64 * HS;
            __half* Vn = Vbuf + ((jt + 1) & 1) * 64 * HS;
            const int tok0 = (jt + 1) * 64;
            #pragma unroll
            for (int i = 0; i < 2; i++) {
                const int cid = t + i * 256;
                const int row = cid >> 3, seg = (cid & 7) * 8;
                cp_async16(&Kn[row * HS + seg],
                           Kb + (size_t)(b * SEQ + tok0 + row) * D_MODEL + hcol + seg);
                cp_async16(&Vn[row * HS + seg],
                           Vbase + (size_t)row * SEQ + tok0 + seg);
            }
        }
        CP_COMMIT();
        CP_WAIT1();
        __syncthreads();

        float sfr[8][4];
        #pragma unroll
        for (int n = 0; n < 8; n++)
            sfr[n][0] = sfr[n][1] = sfr[n][2] = sfr[n][3] = 0.f;
        {
            const __half* kB = Kc + koff;
            #pragma unroll
            for (int kk = 0; kk < 4; kk++) {
                #pragma unroll
                for (int jp = 0; jp < 4; jp++) {
                    unsigned rb[4];
                    ldsm4(rb[0], rb[1], rb[2], rb[3], kB + jp * 16 * HS + kk * 16);
                    mma16h(sfr[jp * 2],     qa[kk], rb[0], rb[1]);
                    mma16h(sfr[jp * 2 + 1], qa[kk], rb[2], rb[3]);
                }
            }
        }

        float mx0 = -1e30f, mx1 = -1e30f;
        #pragma unroll
        for (int n = 0; n < 8; n++) {
            mx0 = fmaxf(mx0, fmaxf(sfr[n][0], sfr[n][1]));
            mx1 = fmaxf(mx1, fmaxf(sfr[n][2], sfr[n][3]));
        }
        mx0 = fmaxf(mx0, __shfl_xor_sync(0xffffffffu, mx0, 1));
        mx0 = fmaxf(mx0, __shfl_xor_sync(0xffffffffu, mx0, 2));
        mx1 = fmaxf(mx1, __shfl_xor_sync(0xffffffffu, mx1, 1));
        mx1 = fmaxf(mx1, __shfl_xor_sync(0xffffffffu, mx1, 2));

        const float mn0 = fmaxf(m0r, mx0);
        const float mn1 = fmaxf(m1r, mx1);
        const float a0 = __expf(m0r - mn0);
        const float a1 = __expf(m1r - mn1);
        m0r = mn0; m1r = mn1;

        float s0 = 0.f, s1 = 0.f;
        #pragma unroll
        for (int n = 0; n < 8; n++) {
            sfr[n][0] = __expf(sfr[n][0] - mn0);
            sfr[n][1] = __expf(sfr[n][1] - mn0);
            sfr[n][2] = __expf(sfr[n][2] - mn1);
            sfr[n][3] = __expf(sfr[n][3] - mn1);
            s0 += sfr[n][0] + sfr[n][1];
            s1 += sfr[n][2] + sfr[n][3];
            of[n][0] *= a0; of[n][1] *= a0;
            of[n][2] *= a1; of[n][3] *= a1;
            *(__half2*)&Ps[(w * 16 + g4)     * HS + n * 8 + 2 * q4] =
                __floats2half2_rn(sfr[n][0], sfr[n][1]);
            *(__half2*)&Ps[(w * 16 + g4 + 8) * HS + n * 8 + 2 * q4] =
                __floats2half2_rn(sfr[n][2], sfr[n][3]);
        }
        s0 += __shfl_xor_sync(0xffffffffu, s0, 1);
        s0 += __shfl_xor_sync(0xffffffffu, s0, 2);
        s1 += __shfl_xor_sync(0xffffffffu, s1, 1);
        s1 += __shfl_xor_sync(0xffffffffu, s1, 2);
        l0r = l0r * a0 + s0;
        l1r = l1r * a1 + s1;
        __syncwarp();

        {
            const __half* pB = Ps + (w * 16) * HS + poff;
            const __half* vB = Vc + koff;
            #pragma unroll
            for (int kk = 0; kk < 4; kk++) {
                unsigned pa[4];
                ldsm4(pa[0], pa[1], pa[2], pa[3], pB + kk * 16);
                #pragma unroll
                for (int jp = 0; jp < 4; jp++) {
                    unsigned rb[4];
                    ldsm4(rb[0], rb[1], rb[2], rb[3], vB + jp * 16 * HS + kk * 16);
                    mma16h(of[jp * 2],     pa, rb[0], rb[1]);
                    mma16h(of[jp * 2 + 1], pa, rb[2], rb[3]);
                }
            }
        }
        __syncwarp();
        __syncthreads();
    }

    const float inv0 = 1.f / l0r;
    const float inv1 = 1.f / l1r;
    const int r0 = base_q + w * 16 + g4;
    #pragma unroll
    for (int n = 0; n < 8; n++) {
        const int c = hcol + n * 8 + 2 * q4;
        *(__half2*)(Ob + (size_t)r0 * D_MODEL + c) =
            __floats2half2_rn(of[n][0] * inv0, of[n][1] * inv0);
        *(__half2*)(Ob + (size_t)(r0 + 8) * D_MODEL + c) =
            __floats2half2_rn(of[n][2] * inv1, of[n][3] * inv1);
    }
}

// ---------------------------------------------------------------------------
extern "C" void kernel_launch(void* const* d_in, const int* in_sizes, int n_in,
                              void* d_out, int out_size)
{
    const float* query = (const float*)d_in[0];
    const float* key   = (const float*)d_in[1];
    const float* value = (const float*)d_in[2];
    const float* Wq    = (const float*)d_in[3];
    const float* bq    = (const float*)d_in[4];
    const float* Wk    = (const float*)d_in[5];
    const float* bk    = (const float*)d_in[6];
    const float* Wv    = (const float*)d_in[7];
    const float* bv    = (const float*)d_in[8];
    const float* Wo    = (const float*)d_in[9];
    const float* bo    = (const float*)d_in[10];
    float* out = (float*)d_out;

    __half *pQ, *pK, *pVt, *pA;
    __half *hXq, *hXk, *hXv, *hWq, *hWk, *hWv, *hWo;
    cudaGetSymbolAddress((void**)&pQ, g_Q);
    cudaGetSymbolAddress((void**)&pK, g_K);
    cudaGetSymbolAddress((void**)&pVt, g_Vt);
    cudaGetSymbolAddress((void**)&pA, g_Attn);
    cudaGetSymbolAddress((void**)&hXq, g_hXq);
    cudaGetSymbolAddress((void**)&hXk, g_hXk);
    cudaGetSymbolAddress((void**)&hXv, g_hXv);
    cudaGetSymbolAddress((void**)&hWq, g_hWq);
    cudaGetSymbolAddress((void**)&hWk, g_hWk);
    cudaGetSymbolAddress((void**)&hWv, g_hWv);
    cudaGetSymbolAddress((void**)&hWo, g_hWo);

    cudaFuncSetAttribute((const void*)gemm_hcp<0>,
                         cudaFuncAttributeMaxDynamicSharedMemorySize, GEMMH_SMEM);
    cudaFuncSetAttribute((const void*)gemm_hcp<1>,
                         cudaFuncAttributeMaxDynamicSharedMemorySize, GEMMH_SMEM);
    cudaFuncSetAttribute((const void*)gemm_hcp<2>,
                         cudaFuncAttributeMaxDynamicSharedMemorySize, GEMMH_SMEM);
    cudaFuncSetAttribute((const void*)attn_h,
                         cudaFuncAttributeMaxDynamicSharedMemorySize, ATTN_SMEM);

    // --- f32 -> f16 pre-conversion (single launch, z = tensor id) ---
    dim3 cg((MTOT * D_MODEL / 8) / 256, 1, 7);      // (2048, 1, 7)
    f2h_all<<<cg, 256>>>(query, key, value, Wq, Wk, Wv, Wo,
                         hXq, hXk, hXv, hWq, hWk, hWv, hWo);

    dim3 gemm_grid(D_MODEL / 128, MTOT / 64);    // (8, 64) = 512 CTAs
    const float qscale = 0.125f;                 // 1/sqrt(64)

    gemm_hcp<1><<<gemm_grid, 256, GEMMH_SMEM>>>(hXq, hWq, bq, qscale, pQ);
    gemm_hcp<1><<<gemm_grid, 256, GEMMH_SMEM>>>(hXk, hWk, bk, 1.f,    pK);
    gemm_hcp<2><<<gemm_grid, 256, GEMMH_SMEM>>>(hXv, hWv, bv, 1.f,    pVt);

    dim3 attn_grid(SEQ / 128, NHEAD, BATCH);     // (16, 16, 2)
    attn_h<<<attn_grid, 256, ATTN_SMEM>>>(pQ, pK, pVt, pA);

    gemm_hcp<0><<<gemm_grid, 256, GEMMH_SMEM>>>(pA, hWo, bo, 1.f, out);
}